// round 5
// baseline (speedup 1.0000x reference)
#include <cuda_runtime.h>
#include <cuda_bf16.h>
#include <cstdint>

#define BATCH 16
#define NV    20000
#define FIN   64
#define COUT  64
#define KNB   16

// Scratch: y = x @ Wn in bf16, packed 2 channels per uint32. [B][V][COUT/2]
__device__ uint32_t g_y[(size_t)BATCH * NV * (COUT / 2)];
// Weights in mma-fragment order: [mat(2)][ks(8)][nt(8)][lane(32)][2] tf32 bits
__device__ uint32_t g_wfrag[2 * 8 * 8 * 32 * 2];

// ---------------------------------------------------------------------------
// Pre-kernel: swizzle Wx/Wn into m16n8k8 B-fragment order (tf32)
// ---------------------------------------------------------------------------
__global__ void wfrag_build_kernel(const float* __restrict__ Wx,
                                   const float* __restrict__ Wn)
{
    int i = blockIdx.x * 256 + threadIdx.x;        // 0..16383
    int j    =  i        & 1;
    int lane = (i >> 1)  & 31;
    int nt   = (i >> 6)  & 7;
    int ks   = (i >> 9)  & 7;
    int mat  =  i >> 12;
    int k = (lane & 3) + 4 * j + 8 * ks;
    int n = (lane >> 2) + 8 * nt;
    const float* W = mat ? Wn : Wx;
    float v = W[k * COUT + n];
    uint32_t tv;
    asm("cvt.rna.tf32.f32 %0, %1;" : "=r"(tv) : "f"(v));
    g_wfrag[i] = tv;
}

// ---------------------------------------------------------------------------
// Kernel A: tensor-core dual GEMM. out = x@Wx + b (d_out), y = x@Wn (bf16)
// CTA = 128 verts x 64 cols, 8 warps; warp = 16 verts x 64 cols, K=64.
// ---------------------------------------------------------------------------
__global__ __launch_bounds__(256)
void gemm_tc_kernel(const float* __restrict__ x,
                    const float* __restrict__ bias,
                    float*       __restrict__ out)
{
    __shared__ uint32_t sW[2 * 8 * 8 * 32 * 2];    // 32 KB

    const int tid = threadIdx.x;

    // Stage fragment-ordered weights: 2048 uint4, 8 per thread, coalesced.
    {
        const uint4* src = (const uint4*)g_wfrag;
        uint4*       dst = (uint4*)sW;
        #pragma unroll
        for (int i = 0; i < 8; ++i)
            dst[tid + i * 256] = src[tid + i * 256];
    }
    __syncthreads();

    const int lane = tid & 31;
    const int wid  = tid >> 5;
    const int g    = lane >> 2;      // group id (row within m-tile)
    const int t    = lane & 3;       // thread-in-group (col phase)
    const int b    = blockIdx.y;
    const int vb   = blockIdx.x * 128 + wid * 16;
    const int r0   = vb + g;
    const int r1   = r0 + 8;

    const float* __restrict__ xb = x + (size_t)b * NV * FIN;

    // ---- Prefetch A: 2 rows x 16 cols (cols == t mod 4). 32 indep LDG.32 --
    float f0[16], f1[16];
    #pragma unroll
    for (int j = 0; j < 16; ++j) {
        int c = t + 4 * j;
        f0[j] = (r0 < NV) ? __ldg(&xb[(size_t)r0 * FIN + c]) : 0.f;
        f1[j] = (r1 < NV) ? __ldg(&xb[(size_t)r1 * FIN + c]) : 0.f;
    }
    uint32_t ar0[16], ar1[16];
    #pragma unroll
    for (int j = 0; j < 16; ++j) {
        asm("cvt.rna.tf32.f32 %0, %1;" : "=r"(ar0[j]) : "f"(f0[j]));
        asm("cvt.rna.tf32.f32 %0, %1;" : "=r"(ar1[j]) : "f"(f1[j]));
    }

    // ---- Mainloop: 8 k-steps x 8 n-tiles x 2 matrices ----------------------
    float accX[8][4] = {{0.f}};
    float accN[8][4] = {{0.f}};

    #pragma unroll
    for (int ks = 0; ks < 8; ++ks) {
        const uint32_t a0 = ar0[2 * ks];
        const uint32_t a1 = ar1[2 * ks];
        const uint32_t a2 = ar0[2 * ks + 1];
        const uint32_t a3 = ar1[2 * ks + 1];

        #pragma unroll
        for (int nt = 0; nt < 8; ++nt) {
            const uint2 bx = *(const uint2*)&sW[((0 * 8 + ks) * 8 + nt) * 64 + lane * 2];
            const uint2 bn = *(const uint2*)&sW[((1 * 8 + ks) * 8 + nt) * 64 + lane * 2];

            asm volatile(
                "mma.sync.aligned.m16n8k8.row.col.f32.tf32.tf32.f32 "
                "{%0,%1,%2,%3}, {%4,%5,%6,%7}, {%8,%9}, {%0,%1,%2,%3};"
                : "+f"(accX[nt][0]), "+f"(accX[nt][1]),
                  "+f"(accX[nt][2]), "+f"(accX[nt][3])
                : "r"(a0), "r"(a1), "r"(a2), "r"(a3),
                  "r"(bx.x), "r"(bx.y));
            asm volatile(
                "mma.sync.aligned.m16n8k8.row.col.f32.tf32.tf32.f32 "
                "{%0,%1,%2,%3}, {%4,%5,%6,%7}, {%8,%9}, {%0,%1,%2,%3};"
                : "+f"(accN[nt][0]), "+f"(accN[nt][1]),
                  "+f"(accN[nt][2]), "+f"(accN[nt][3])
                : "r"(a0), "r"(a1), "r"(a2), "r"(a3),
                  "r"(bn.x), "r"(bn.y));
        }
    }

    // ---- Epilogue: c0/c1 = row g cols (8nt+2t, +1); c2/c3 = row g+8 --------
    float*    __restrict__ outb = out + (size_t)b * NV * COUT;
    uint32_t* __restrict__ yb   = g_y + (size_t)b * NV * (COUT / 2);
    #pragma unroll
    for (int nt = 0; nt < 8; ++nt) {
        const int c  = nt * 8 + 2 * t;
        const int ch = nt * 4 + t;        // packed half-index c/2
        const float2 bv = *(const float2*)&bias[c];
        if (r0 < NV) {
            *(float2*)&outb[(size_t)r0 * COUT + c] =
                make_float2(accX[nt][0] + bv.x, accX[nt][1] + bv.y);
            __nv_bfloat162 p = __float22bfloat162_rn(
                make_float2(accN[nt][0], accN[nt][1]));
            yb[(size_t)r0 * (COUT / 2) + ch] = *(uint32_t*)&p;
        }
        if (r1 < NV) {
            *(float2*)&outb[(size_t)r1 * COUT + c] =
                make_float2(accX[nt][2] + bv.x, accX[nt][3] + bv.y);
            __nv_bfloat162 p = __float22bfloat162_rn(
                make_float2(accN[nt][2], accN[nt][3]));
            yb[(size_t)r1 * (COUT / 2) + ch] = *(uint32_t*)&p;
        }
    }
}

// ---------------------------------------------------------------------------
// Kernel B: out[b,v,:] += (1/K) * sum_k y[b, neighbor[v,k]-1, :]   (0 = pad)
// One warp per (b, v). Each neighbor row = 128 B bf16, one LDG.32 per lane.
// ---------------------------------------------------------------------------
__global__ __launch_bounds__(256)
void gather_add_kernel(const int* __restrict__ neighbor,
                       float*     __restrict__ out)
{
    const int tid  = threadIdx.x;
    const int warp = tid >> 5;
    const int lane = tid & 31;
    const int v    = blockIdx.x * 8 + warp;     // 2500 * 8 = 20000 exactly
    const int b    = blockIdx.y;

    const uint32_t* __restrict__ yb = g_y + (size_t)b * NV * (COUT / 2);
    float* __restrict__ op = out + ((size_t)b * NV + v) * COUT + lane * 2;

    float2 o = *(const float2*)op;   // x@Wx + bias part

    int nid = 0;
    if (lane < KNB)
        nid = __ldg(&neighbor[v * KNB + lane]);

    float2 acc = make_float2(0.f, 0.f);
    #pragma unroll
    for (int k = 0; k < KNB; ++k) {
        int r = __shfl_sync(0xffffffffu, nid, k);
        if (r > 0) {
            uint32_t w = __ldg(&yb[(size_t)(r - 1) * (COUT / 2) + lane]);
            // exact bf16 -> fp32: low half = w<<16, high half = w & 0xffff0000
            acc.x += __uint_as_float(w << 16);
            acc.y += __uint_as_float(w & 0xffff0000u);
        }
    }

    const float s = 1.0f / (float)KNB;
    o.x += acc.x * s;
    o.y += acc.y * s;
    *(float2*)op = o;
}

extern "C" void kernel_launch(void* const* d_in, const int* in_sizes, int n_in,
                              void* d_out, int out_size)
{
    // metadata order: x, Wx, Wn, b, neighbor
    const float* x        = (const float*)d_in[0];
    const float* Wx       = (const float*)d_in[1];
    const float* Wn       = (const float*)d_in[2];
    const float* bias     = (const float*)d_in[3];
    const int*   neighbor = (const int*)d_in[4];
    float*       out      = (float*)d_out;

    wfrag_build_kernel<<<64, 256>>>(Wx, Wn);

    dim3 gridA((NV + 127) / 128, BATCH);        // 157 x 16
    gemm_tc_kernel<<<gridA, 256>>>(x, bias, out);

    dim3 gridB(NV / 8, BATCH);                  // 2500 x 16
    gather_add_kernel<<<gridB, 256>>>(neighbor, out);
}

// round 6
// speedup vs baseline: 1.2115x; 1.2115x over previous
#include <cuda_runtime.h>
#include <cstdint>

#define BATCH 16
#define NV    20000
#define FIN   64
#define COUT  64
#define KNB   16

// Scratch: y = x @ Wn, [B][V][COUT]
__device__ float g_y[(size_t)BATCH * NV * COUT];
// Weights in mma-fragment order: [mat(2)][ks(8)][nt(8)][lane(32)][2] tf32 bits
__device__ uint32_t g_wfrag[2 * 8 * 8 * 32 * 2];

// ---------------------------------------------------------------------------
// Pre-kernel: swizzle Wx/Wn into m16n8k8 B-fragment order (tf32)
// ---------------------------------------------------------------------------
__global__ void wfrag_build_kernel(const float* __restrict__ Wx,
                                   const float* __restrict__ Wn)
{
    int i = blockIdx.x * 256 + threadIdx.x;        // 0..16383
    int j    =  i        & 1;
    int lane = (i >> 1)  & 31;
    int nt   = (i >> 6)  & 7;
    int ks   = (i >> 9)  & 7;
    int mat  =  i >> 12;
    int k = (lane & 3) + 4 * j + 8 * ks;
    int n = (lane >> 2) + 8 * nt;
    const float* W = mat ? Wn : Wx;
    float v = W[k * COUT + n];
    uint32_t tv;
    asm("cvt.rna.tf32.f32 %0, %1;" : "=r"(tv) : "f"(v));
    g_wfrag[i] = tv;
}

// ---------------------------------------------------------------------------
// Kernel A: tensor-core dual GEMM. out = x@Wx + b (d_out), y = x@Wn (scratch)
// CTA = 128 verts x 64 cols, 8 warps; warp = 16 verts x 64 cols, K=64.
// ---------------------------------------------------------------------------
__global__ __launch_bounds__(256)
void gemm_tc_kernel(const float* __restrict__ x,
                    const float* __restrict__ bias,
                    float*       __restrict__ out)
{
    __shared__ uint32_t sW[2 * 8 * 8 * 32 * 2];    // 32 KB

    const int tid = threadIdx.x;

    // Stage fragment-ordered weights: 2048 uint4, 8 per thread, coalesced.
    {
        const uint4* src = (const uint4*)g_wfrag;
        uint4*       dst = (uint4*)sW;
        #pragma unroll
        for (int i = 0; i < 8; ++i)
            dst[tid + i * 256] = src[tid + i * 256];
    }
    __syncthreads();

    const int lane = tid & 31;
    const int wid  = tid >> 5;
    const int g    = lane >> 2;      // group id (row within m-tile)
    const int t    = lane & 3;       // thread-in-group (col phase)
    const int b    = blockIdx.y;
    const int vb   = blockIdx.x * 128 + wid * 16;
    const int r0   = vb + g;
    const int r1   = r0 + 8;

    const float* __restrict__ xb = x + (size_t)b * NV * FIN;

    // ---- Prefetch A: 2 rows x 16 cols (cols == t mod 4). 32 indep LDG.32 --
    float f0[16], f1[16];
    #pragma unroll
    for (int j = 0; j < 16; ++j) {
        int c = t + 4 * j;
        f0[j] = (r0 < NV) ? __ldg(&xb[(size_t)r0 * FIN + c]) : 0.f;
        f1[j] = (r1 < NV) ? __ldg(&xb[(size_t)r1 * FIN + c]) : 0.f;
    }
    uint32_t ar0[16], ar1[16];
    #pragma unroll
    for (int j = 0; j < 16; ++j) {
        asm("cvt.rna.tf32.f32 %0, %1;" : "=r"(ar0[j]) : "f"(f0[j]));
        asm("cvt.rna.tf32.f32 %0, %1;" : "=r"(ar1[j]) : "f"(f1[j]));
    }

    // ---- Mainloop: 8 k-steps x 8 n-tiles x 2 matrices ----------------------
    float accX[8][4] = {{0.f}};
    float accN[8][4] = {{0.f}};

    #pragma unroll
    for (int ks = 0; ks < 8; ++ks) {
        const uint32_t a0 = ar0[2 * ks];
        const uint32_t a1 = ar1[2 * ks];
        const uint32_t a2 = ar0[2 * ks + 1];
        const uint32_t a3 = ar1[2 * ks + 1];

        #pragma unroll
        for (int nt = 0; nt < 8; ++nt) {
            const uint2 bx = *(const uint2*)&sW[((0 * 8 + ks) * 8 + nt) * 64 + lane * 2];
            const uint2 bn = *(const uint2*)&sW[((1 * 8 + ks) * 8 + nt) * 64 + lane * 2];

            asm volatile(
                "mma.sync.aligned.m16n8k8.row.col.f32.tf32.tf32.f32 "
                "{%0,%1,%2,%3}, {%4,%5,%6,%7}, {%8,%9}, {%0,%1,%2,%3};"
                : "+f"(accX[nt][0]), "+f"(accX[nt][1]),
                  "+f"(accX[nt][2]), "+f"(accX[nt][3])
                : "r"(a0), "r"(a1), "r"(a2), "r"(a3),
                  "r"(bx.x), "r"(bx.y));
            asm volatile(
                "mma.sync.aligned.m16n8k8.row.col.f32.tf32.tf32.f32 "
                "{%0,%1,%2,%3}, {%4,%5,%6,%7}, {%8,%9}, {%0,%1,%2,%3};"
                : "+f"(accN[nt][0]), "+f"(accN[nt][1]),
                  "+f"(accN[nt][2]), "+f"(accN[nt][3])
                : "r"(a0), "r"(a1), "r"(a2), "r"(a3),
                  "r"(bn.x), "r"(bn.y));
        }
    }

    // ---- Epilogue: c0/c1 = row g cols (8nt+2t, +1); c2/c3 = row g+8 --------
    float* __restrict__ outb = out + (size_t)b * NV * COUT;
    float* __restrict__ yb   = g_y + (size_t)b * NV * COUT;
    #pragma unroll
    for (int nt = 0; nt < 8; ++nt) {
        const int c = nt * 8 + 2 * t;
        const float2 bv = *(const float2*)&bias[c];
        if (r0 < NV) {
            *(float2*)&outb[(size_t)r0 * COUT + c] =
                make_float2(accX[nt][0] + bv.x, accX[nt][1] + bv.y);
            *(float2*)&yb[(size_t)r0 * COUT + c] =
                make_float2(accN[nt][0], accN[nt][1]);
        }
        if (r1 < NV) {
            *(float2*)&outb[(size_t)r1 * COUT + c] =
                make_float2(accX[nt][2] + bv.x, accX[nt][3] + bv.y);
            *(float2*)&yb[(size_t)r1 * COUT + c] =
                make_float2(accN[nt][2], accN[nt][3]);
        }
    }
}

// ---------------------------------------------------------------------------
// Kernel B: out[b,v,:] += (1/K) * sum_k y[b, neighbor[v,k]-1, :]   (0 = pad)
// One warp per TWO vertices (v0, v0+1): 32 independent LDG.64 in flight.
// Neighbor lists for both vertices come from one coalesced 128B read.
// ---------------------------------------------------------------------------
__global__ __launch_bounds__(256)
void gather_add_kernel(const int* __restrict__ neighbor,
                       float*     __restrict__ out)
{
    const int tid  = threadIdx.x;
    const int warp = tid >> 5;
    const int lane = tid & 31;
    const int v0   = blockIdx.x * 16 + warp * 2;   // 1250 * 16 = 20000 exactly
    const int b    = blockIdx.y;

    const float* __restrict__ yb = g_y + (size_t)b * NV * COUT;

    float* __restrict__ op0 = out + ((size_t)b * NV + v0)     * COUT + lane * 2;
    float* __restrict__ op1 = out + ((size_t)b * NV + v0 + 1) * COUT + lane * 2;

    // One coalesced read: lanes 0-15 -> v0's list, lanes 16-31 -> (v0+1)'s.
    int nid = __ldg(&neighbor[v0 * KNB + lane]);

    float2 o0 = *(const float2*)op0;   // x@Wx + bias parts
    float2 o1 = *(const float2*)op1;

    float2 acc0 = make_float2(0.f, 0.f);
    float2 acc1 = make_float2(0.f, 0.f);

    #pragma unroll
    for (int k = 0; k < KNB; ++k) {
        int ra = __shfl_sync(0xffffffffu, nid, k);        // v0's neighbor k
        int rb = __shfl_sync(0xffffffffu, nid, k + 16);   // v1's neighbor k
        if (ra > 0) {
            float2 t0 = *(const float2*)(yb + (size_t)(ra - 1) * COUT + lane * 2);
            acc0.x += t0.x; acc0.y += t0.y;
        }
        if (rb > 0) {
            float2 t1 = *(const float2*)(yb + (size_t)(rb - 1) * COUT + lane * 2);
            acc1.x += t1.x; acc1.y += t1.y;
        }
    }

    const float s = 1.0f / (float)KNB;
    o0.x += acc0.x * s;  o0.y += acc0.y * s;
    o1.x += acc1.x * s;  o1.y += acc1.y * s;
    *(float2*)op0 = o0;
    *(float2*)op1 = o1;
}

extern "C" void kernel_launch(void* const* d_in, const int* in_sizes, int n_in,
                              void* d_out, int out_size)
{
    // metadata order: x, Wx, Wn, b, neighbor
    const float* x        = (const float*)d_in[0];
    const float* Wx       = (const float*)d_in[1];
    const float* Wn       = (const float*)d_in[2];
    const float* bias     = (const float*)d_in[3];
    const int*   neighbor = (const int*)d_in[4];
    float*       out      = (float*)d_out;

    wfrag_build_kernel<<<64, 256>>>(Wx, Wn);

    dim3 gridA((NV + 127) / 128, BATCH);        // 157 x 16
    gemm_tc_kernel<<<gridA, 256>>>(x, bias, out);

    dim3 gridB(NV / 16, BATCH);                 // 1250 x 16
    gather_add_kernel<<<gridB, 256>>>(neighbor, out);
}

// round 7
// speedup vs baseline: 1.2160x; 1.0037x over previous
#include <cuda_runtime.h>
#include <cstdint>

#define BATCH 16
#define NV    20000
#define FIN   64
#define COUT  64
#define KNB   16

// Scratch: y = x @ Wn, [B][V][COUT]
__device__ float g_y[(size_t)BATCH * NV * COUT];
// Weights in mma-fragment order: [mat(2)][ks(8)][nt(8)][lane(32)][2] tf32 bits
__device__ uint32_t g_wfrag[2 * 8 * 8 * 32 * 2];

// ---------------------------------------------------------------------------
// Pre-kernel: swizzle Wx/Wn into m16n8k8 B-fragment order (tf32)
// ---------------------------------------------------------------------------
__global__ void wfrag_build_kernel(const float* __restrict__ Wx,
                                   const float* __restrict__ Wn)
{
    int i = blockIdx.x * 256 + threadIdx.x;        // 0..16383
    int j    =  i        & 1;
    int lane = (i >> 1)  & 31;
    int nt   = (i >> 6)  & 7;
    int ks   = (i >> 9)  & 7;
    int mat  =  i >> 12;
    int k = (lane & 3) + 4 * j + 8 * ks;
    int n = (lane >> 2) + 8 * nt;
    const float* W = mat ? Wn : Wx;
    float v = W[k * COUT + n];
    uint32_t tv;
    asm("cvt.rna.tf32.f32 %0, %1;" : "=r"(tv) : "f"(v));
    g_wfrag[i] = tv;
}

// ---------------------------------------------------------------------------
// Kernel A: tensor-core dual GEMM. out = x@Wx + b (d_out), y = x@Wn (scratch)
// CTA = 128 verts x 64 cols, 8 warps; warp = 16 verts x 64 cols, K=64.
// ---------------------------------------------------------------------------
__global__ __launch_bounds__(256)
void gemm_tc_kernel(const float* __restrict__ x,
                    const float* __restrict__ bias,
                    float*       __restrict__ out)
{
    __shared__ uint32_t sW[2 * 8 * 8 * 32 * 2];    // 32 KB

    const int tid = threadIdx.x;

    // Stage fragment-ordered weights: 2048 uint4, 8 per thread, coalesced.
    {
        const uint4* src = (const uint4*)g_wfrag;
        uint4*       dst = (uint4*)sW;
        #pragma unroll
        for (int i = 0; i < 8; ++i)
            dst[tid + i * 256] = src[tid + i * 256];
    }
    __syncthreads();

    const int lane = tid & 31;
    const int wid  = tid >> 5;
    const int g    = lane >> 2;      // group id (row within m-tile)
    const int t    = lane & 3;       // thread-in-group (col phase)
    const int b    = blockIdx.y;
    const int vb   = blockIdx.x * 128 + wid * 16;
    const int r0   = vb + g;
    const int r1   = r0 + 8;

    const float* __restrict__ xb = x + (size_t)b * NV * FIN;

    // ---- Prefetch A: 2 rows x 16 cols (cols == t mod 4). 32 indep LDG.32 --
    float f0[16], f1[16];
    #pragma unroll
    for (int j = 0; j < 16; ++j) {
        int c = t + 4 * j;
        f0[j] = (r0 < NV) ? __ldg(&xb[(size_t)r0 * FIN + c]) : 0.f;
        f1[j] = (r1 < NV) ? __ldg(&xb[(size_t)r1 * FIN + c]) : 0.f;
    }
    uint32_t ar0[16], ar1[16];
    #pragma unroll
    for (int j = 0; j < 16; ++j) {
        asm("cvt.rna.tf32.f32 %0, %1;" : "=r"(ar0[j]) : "f"(f0[j]));
        asm("cvt.rna.tf32.f32 %0, %1;" : "=r"(ar1[j]) : "f"(f1[j]));
    }

    // ---- Mainloop: 8 k-steps x 8 n-tiles x 2 matrices ----------------------
    float accX[8][4] = {{0.f}};
    float accN[8][4] = {{0.f}};

    #pragma unroll
    for (int ks = 0; ks < 8; ++ks) {
        const uint32_t a0 = ar0[2 * ks];
        const uint32_t a1 = ar1[2 * ks];
        const uint32_t a2 = ar0[2 * ks + 1];
        const uint32_t a3 = ar1[2 * ks + 1];

        #pragma unroll
        for (int nt = 0; nt < 8; ++nt) {
            const uint2 bx = *(const uint2*)&sW[((0 * 8 + ks) * 8 + nt) * 64 + lane * 2];
            const uint2 bn = *(const uint2*)&sW[((1 * 8 + ks) * 8 + nt) * 64 + lane * 2];

            asm volatile(
                "mma.sync.aligned.m16n8k8.row.col.f32.tf32.tf32.f32 "
                "{%0,%1,%2,%3}, {%4,%5,%6,%7}, {%8,%9}, {%0,%1,%2,%3};"
                : "+f"(accX[nt][0]), "+f"(accX[nt][1]),
                  "+f"(accX[nt][2]), "+f"(accX[nt][3])
                : "r"(a0), "r"(a1), "r"(a2), "r"(a3),
                  "r"(bx.x), "r"(bx.y));
            asm volatile(
                "mma.sync.aligned.m16n8k8.row.col.f32.tf32.tf32.f32 "
                "{%0,%1,%2,%3}, {%4,%5,%6,%7}, {%8,%9}, {%0,%1,%2,%3};"
                : "+f"(accN[nt][0]), "+f"(accN[nt][1]),
                  "+f"(accN[nt][2]), "+f"(accN[nt][3])
                : "r"(a0), "r"(a1), "r"(a2), "r"(a3),
                  "r"(bn.x), "r"(bn.y));
        }
    }

    // ---- Epilogue: c0/c1 = row g cols (8nt+2t, +1); c2/c3 = row g+8 --------
    float* __restrict__ outb = out + (size_t)b * NV * COUT;
    float* __restrict__ yb   = g_y + (size_t)b * NV * COUT;
    #pragma unroll
    for (int nt = 0; nt < 8; ++nt) {
        const int c = nt * 8 + 2 * t;
        const float2 bv = *(const float2*)&bias[c];
        if (r0 < NV) {
            *(float2*)&outb[(size_t)r0 * COUT + c] =
                make_float2(accX[nt][0] + bv.x, accX[nt][1] + bv.y);
            *(float2*)&yb[(size_t)r0 * COUT + c] =
                make_float2(accN[nt][0], accN[nt][1]);
        }
        if (r1 < NV) {
            *(float2*)&outb[(size_t)r1 * COUT + c] =
                make_float2(accX[nt][2] + bv.x, accX[nt][3] + bv.y);
            *(float2*)&yb[(size_t)r1 * COUT + c] =
                make_float2(accN[nt][2], accN[nt][3]);
        }
    }
}

// ---------------------------------------------------------------------------
// Kernel B: out[b,v,:] += (1/K) * sum_k y[b, neighbor[v,k]-1, :]   (0 = pad)
// One warp per FOUR vertices: up to 64 independent LDG.64 in flight.
// All 4 neighbor lists come from one coalesced 256B int2 read.
// ---------------------------------------------------------------------------
__global__ __launch_bounds__(256)
void gather_add_kernel(const int* __restrict__ neighbor,
                       float*     __restrict__ out)
{
    const int tid  = threadIdx.x;
    const int warp = tid >> 5;
    const int lane = tid & 31;
    const int v0   = blockIdx.x * 32 + warp * 4;   // 625 * 32 = 20000 exactly
    const int b    = blockIdx.y;

    const float* __restrict__ yb = g_y + (size_t)b * NV * COUT;

    // One coalesced 256B read: lane l holds ids {2l, 2l+1} of the 64-id block.
    // Vertex j's list (16 ids) lives in lanes 8j..8j+7, components x,y.
    const int2 nid2 = __ldg((const int2*)&neighbor[v0 * KNB] + lane);

    float* __restrict__ op0 = out + ((size_t)b * NV + v0 + 0) * COUT + lane * 2;
    float* __restrict__ op1 = out + ((size_t)b * NV + v0 + 1) * COUT + lane * 2;
    float* __restrict__ op2 = out + ((size_t)b * NV + v0 + 2) * COUT + lane * 2;
    float* __restrict__ op3 = out + ((size_t)b * NV + v0 + 3) * COUT + lane * 2;

    float2 o0 = *(const float2*)op0;   // x@Wx + bias parts
    float2 o1 = *(const float2*)op1;
    float2 o2 = *(const float2*)op2;
    float2 o3 = *(const float2*)op3;

    float2 a0 = make_float2(0.f, 0.f);
    float2 a1 = make_float2(0.f, 0.f);
    float2 a2 = make_float2(0.f, 0.f);
    float2 a3 = make_float2(0.f, 0.f);

    #pragma unroll
    for (int k = 0; k < KNB; ++k) {
        const int src = k >> 1;                      // lane offset within list
        const int xlo = __shfl_sync(0xffffffffu, nid2.x, src +  0);
        const int ylo = __shfl_sync(0xffffffffu, nid2.y, src +  0);
        const int x1_ = __shfl_sync(0xffffffffu, nid2.x, src +  8);
        const int y1_ = __shfl_sync(0xffffffffu, nid2.y, src +  8);
        const int x2_ = __shfl_sync(0xffffffffu, nid2.x, src + 16);
        const int y2_ = __shfl_sync(0xffffffffu, nid2.y, src + 16);
        const int x3_ = __shfl_sync(0xffffffffu, nid2.x, src + 24);
        const int y3_ = __shfl_sync(0xffffffffu, nid2.y, src + 24);
        const int r0 = (k & 1) ? ylo : xlo;
        const int r1 = (k & 1) ? y1_ : x1_;
        const int r2 = (k & 1) ? y2_ : x2_;
        const int r3 = (k & 1) ? y3_ : x3_;

        if (r0 > 0) {
            float2 t = *(const float2*)(yb + (size_t)(r0 - 1) * COUT + lane * 2);
            a0.x += t.x; a0.y += t.y;
        }
        if (r1 > 0) {
            float2 t = *(const float2*)(yb + (size_t)(r1 - 1) * COUT + lane * 2);
            a1.x += t.x; a1.y += t.y;
        }
        if (r2 > 0) {
            float2 t = *(const float2*)(yb + (size_t)(r2 - 1) * COUT + lane * 2);
            a2.x += t.x; a2.y += t.y;
        }
        if (r3 > 0) {
            float2 t = *(const float2*)(yb + (size_t)(r3 - 1) * COUT + lane * 2);
            a3.x += t.x; a3.y += t.y;
        }
    }

    const float s = 1.0f / (float)KNB;
    o0.x += a0.x * s;  o0.y += a0.y * s;
    o1.x += a1.x * s;  o1.y += a1.y * s;
    o2.x += a2.x * s;  o2.y += a2.y * s;
    o3.x += a3.x * s;  o3.y += a3.y * s;
    *(float2*)op0 = o0;
    *(float2*)op1 = o1;
    *(float2*)op2 = o2;
    *(float2*)op3 = o3;
}

extern "C" void kernel_launch(void* const* d_in, const int* in_sizes, int n_in,
                              void* d_out, int out_size)
{
    // metadata order: x, Wx, Wn, b, neighbor
    const float* x        = (const float*)d_in[0];
    const float* Wx       = (const float*)d_in[1];
    const float* Wn       = (const float*)d_in[2];
    const float* bias     = (const float*)d_in[3];
    const int*   neighbor = (const int*)d_in[4];
    float*       out      = (float*)d_out;

    wfrag_build_kernel<<<64, 256>>>(Wx, Wn);

    dim3 gridA((NV + 127) / 128, BATCH);        // 157 x 16
    gemm_tc_kernel<<<gridA, 256>>>(x, bias, out);

    dim3 gridB(NV / 32, BATCH);                 // 625 x 16
    gather_add_kernel<<<gridB, 256>>>(neighbor, out);
}